// round 9
// baseline (speedup 1.0000x reference)
#include <cuda_runtime.h>
#include <cuda_bf16.h>
#include <cuda_fp16.h>
#include <cstdint>

#define G_NUM 1024
#define D 128

// ---------------------------------------------------------------------------
// Device scratch
// ---------------------------------------------------------------------------
__device__ int   g_segstart[G_NUM + 1];
__device__ float g_sums[G_NUM * D];
__device__ float g_C[G_NUM * D];
// W1 (fp16) in COLUMN-PERMUTED mma B-fragment layout
__device__ __align__(16) uint32_t g_Bf[8192];

// ---------------------------------------------------------------------------
// Helpers
// ---------------------------------------------------------------------------
__device__ __forceinline__ uint32_t pack_f16(float lo, float hi) {
    uint32_t r;
    asm("cvt.rn.f16x2.f32 %0, %1, %2;" : "=r"(r) : "f"(hi), "f"(lo));
    return r;
}
__device__ __forceinline__ float lo_h(uint32_t p) {
    return __half2float(__ushort_as_half((unsigned short)(p & 0xffff)));
}
__device__ __forceinline__ float hi_h(uint32_t p) {
    return __half2float(__ushort_as_half((unsigned short)(p >> 16)));
}

__device__ __forceinline__ void mma_f16(float* d, const uint32_t* a, const uint32_t* b) {
    asm volatile(
        "mma.sync.aligned.m16n8k16.row.col.f32.f16.f16.f32 "
        "{%0,%1,%2,%3}, {%4,%5,%6,%7}, {%8,%9}, {%0,%1,%2,%3};"
        : "+f"(d[0]), "+f"(d[1]), "+f"(d[2]), "+f"(d[3])
        : "r"(a[0]), "r"(a[1]), "r"(a[2]), "r"(a[3]), "r"(b[0]), "r"(b[1]));
}

// ---------------------------------------------------------------------------
// K1: zero sums + segment boundaries + W1 -> permuted fp16 B-fragments
// ---------------------------------------------------------------------------
__global__ void k_prep(const int* __restrict__ bid, int N, const float* __restrict__ W) {
    int i = blockIdx.x * blockDim.x + threadIdx.x;
    if (i < G_NUM * D) g_sums[i] = 0.f;
    if (i < N) {
        int b = bid[i];
        int prev = (i == 0) ? -1 : bid[i - 1];
        for (int g = prev + 1; g <= b; ++g) g_segstart[g] = i;
        if (i == N - 1)
            for (int g = b + 1; g <= G_NUM; ++g) g_segstart[g] = N;
    }
    if (i < 4096) {
        int ks = i >> 9;
        int na = (i >> 5) & 15;
        int l  = i & 31;
        int c  = l & 3;
        int n  = na * 8 + (l >> 2);
        int k0 = ks * 16 + 4 * c;
        const float* wr = W + (size_t)n * 256;
        g_Bf[i * 2 + 0] = pack_f16(wr[k0],     wr[k0 + 1]);
        g_Bf[i * 2 + 1] = pack_f16(wr[k0 + 2], wr[k0 + 3]);
    }
}

// ---------------------------------------------------------------------------
// K2: tile-parallel segment sums with uniform-tile fast path.
// CTA = 256 rows, 256 thr: warp h reads rows h, h+8, ...; lane q owns
// features 4q..4q+3. Uniform tile (sorted bid, sb[0]==sb[255]) -> no branches.
// ---------------------------------------------------------------------------
__global__ void __launch_bounds__(256)
k_sum(const float* __restrict__ x, const int* __restrict__ bid, int N) {
    __shared__ int sb[256];
    int tid = threadIdx.x;
    int n0 = blockIdx.x * 256;
    sb[tid] = (n0 + tid < N) ? bid[n0 + tid] : -1;
    __syncthreads();

    int h = tid >> 5;
    int q = tid & 31;

    if ((n0 + 256 <= N) && (sb[0] == sb[255])) {
        // Fast path: single segment covers the whole tile.
        int b0 = sb[0];
        float4 a0 = make_float4(0.f, 0.f, 0.f, 0.f), a1 = a0;
#pragma unroll
        for (int it = 0; it < 16; ++it) {
            int r = it * 16 + h;
            float4 v0 = *(const float4*)(x + (size_t)(n0 + r) * D + q * 4);
            float4 v1 = *(const float4*)(x + (size_t)(n0 + r + 8) * D + q * 4);
            a0.x += v0.x; a0.y += v0.y; a0.z += v0.z; a0.w += v0.w;
            a1.x += v1.x; a1.y += v1.y; a1.z += v1.z; a1.w += v1.w;
        }
        a0.x += a1.x; a0.y += a1.y; a0.z += a1.z; a0.w += a1.w;
        float* dst = &g_sums[b0 * D + q * 4];
        atomicAdd(dst + 0, a0.x); atomicAdd(dst + 1, a0.y);
        atomicAdd(dst + 2, a0.z); atomicAdd(dst + 3, a0.w);
        return;
    }

    float4 acc = make_float4(0.f, 0.f, 0.f, 0.f);
    int curbid = sb[h];
#pragma unroll 8
    for (int r = h; r < 256; r += 8) {
        int bv = sb[r];
        if (bv != curbid) {
            if (curbid >= 0) {
                float* dst = &g_sums[curbid * D + q * 4];
                atomicAdd(dst + 0, acc.x); atomicAdd(dst + 1, acc.y);
                atomicAdd(dst + 2, acc.z); atomicAdd(dst + 3, acc.w);
            }
            acc = make_float4(0.f, 0.f, 0.f, 0.f);
            curbid = bv;
        }
        if (bv >= 0) {
            float4 v = *(const float4*)(x + (size_t)(n0 + r) * D + q * 4);
            acc.x += v.x; acc.y += v.y; acc.z += v.z; acc.w += v.w;
        }
    }
    if (curbid >= 0) {
        float* dst = &g_sums[curbid * D + q * 4];
        atomicAdd(dst + 0, acc.x); atomicAdd(dst + 1, acc.y);
        atomicAdd(dst + 2, acc.z); atomicAdd(dst + 3, acc.w);
    }
}

// ---------------------------------------------------------------------------
// K3: C[g] = (sums[g]/cnt) @ W2^T + b
// ---------------------------------------------------------------------------
__global__ void k_ctx(const float* __restrict__ W, const float* __restrict__ b) {
    __shared__ float sm[D];
    int g = blockIdx.x, t = threadIdx.x;
    int s = g_segstart[g], e = g_segstart[g + 1];
    int cnt = e - s;
    float inv = 1.f / (float)(cnt > 0 ? cnt : 1);
    sm[t] = g_sums[g * D + t] * inv;
    __syncthreads();
    float c = b[t];
    const float* wrow = W + (size_t)t * 256 + 128;
#pragma unroll 8
    for (int k = 0; k < D; ++k) c += sm[k] * wrow[k];
    g_C[g * D + t] = c;
}

// ---------------------------------------------------------------------------
// K4: fp16x2 mma.sync GEMM  out[n] = x[n] @ W1^T + C[bid[n]]
// CTA tile 256x128, warp = 32 rows x 128 cols (B frag feeds 4 MMAs).
// 1 CTA/SM; ks pairs, register prefetch distance 2.
// ---------------------------------------------------------------------------
#define STG_STRIDE 136
#define SMEM_BYTES (128 * STG_STRIDE * 4)   // 69632 >= 32768 (B frags)

__global__ void __launch_bounds__(256, 1)
k_gemm(const float* __restrict__ x, const int* __restrict__ bid,
       float* __restrict__ out, int N) {
    extern __shared__ __align__(16) uint32_t sh[];
    uint32_t* shB = sh;                      // [8192] u32 fp16 B frags

    int tid = threadIdx.x;
    int w   = tid >> 5;
    int l   = tid & 31;
    int n0  = blockIdx.x * 256;

#pragma unroll
    for (int i = 0; i < 8; ++i) {
        int q = i * 256 + tid;
        *(uint4*)(shB + q * 4) = *(const uint4*)(g_Bf + q * 4);
    }
    __syncthreads();

    int g4 = l >> 2, c4 = l & 3;
    int rb = n0 + w * 32;
    int r[4] = {rb + g4, rb + 8 + g4, rb + 16 + g4, rb + 24 + g4};
    const float* p[4];
    bool vr[4];
    bool full = (n0 + 256) <= N;
#pragma unroll
    for (int j = 0; j < 4; ++j) {
        p[j] = x + (size_t)r[j] * 128;
        vr[j] = full || (r[j] < N);
    }
    const float4 z4 = make_float4(0.f, 0.f, 0.f, 0.f);

    float acc[2][16][4];
#pragma unroll
    for (int mt = 0; mt < 2; ++mt)
#pragma unroll
        for (int na = 0; na < 16; ++na)
#pragma unroll
            for (int j = 0; j < 4; ++j) acc[mt][na][j] = 0.f;

    // A buffers: [s][row j] float4, for a pair of ks steps
    float4 cur[2][4], nxt[2][4];

#define LOAD_PAIR(dst, kp)                                                     \
    do {                                                                       \
        _Pragma("unroll")                                                      \
        for (int s_ = 0; s_ < 2; ++s_) {                                       \
            int k0_ = ((kp) * 2 + s_) * 16 + 4 * c4;                           \
            _Pragma("unroll")                                                  \
            for (int j_ = 0; j_ < 4; ++j_)                                     \
                dst[s_][j_] = vr[j_] ? *(const float4*)(p[j_] + k0_) : z4;     \
        }                                                                      \
    } while (0)

    LOAD_PAIR(cur, 0);

#pragma unroll
    for (int kp = 0; kp < 4; ++kp) {
        if (kp < 3) LOAD_PAIR(nxt, kp + 1);

#pragma unroll
        for (int s = 0; s < 2; ++s) {
            int ks = kp * 2 + s;
            uint32_t ahi[2][4], alo[2][4];
#pragma unroll
            for (int mt = 0; mt < 2; ++mt) {
                float4 u = cur[s][2 * mt + 0];
                float4 v = cur[s][2 * mt + 1];
                ahi[mt][0] = pack_f16(u.x, u.y);
                ahi[mt][1] = pack_f16(v.x, v.y);
                ahi[mt][2] = pack_f16(u.z, u.w);
                ahi[mt][3] = pack_f16(v.z, v.w);
                alo[mt][0] = pack_f16(u.x - lo_h(ahi[mt][0]), u.y - hi_h(ahi[mt][0]));
                alo[mt][1] = pack_f16(v.x - lo_h(ahi[mt][1]), v.y - hi_h(ahi[mt][1]));
                alo[mt][2] = pack_f16(u.z - lo_h(ahi[mt][2]), u.w - hi_h(ahi[mt][2]));
                alo[mt][3] = pack_f16(v.z - lo_h(ahi[mt][3]), v.w - hi_h(ahi[mt][3]));
            }

            const uint32_t* bks = shB + ks * 16 * 64;
#pragma unroll
            for (int na = 0; na < 16; ++na) {
                uint2 bh = *(const uint2*)(bks + na * 64 + l * 2);
                uint32_t bhr[2] = {bh.x, bh.y};
                mma_f16(acc[0][na], ahi[0], bhr);
                mma_f16(acc[0][na], alo[0], bhr);
                mma_f16(acc[1][na], ahi[1], bhr);
                mma_f16(acc[1][na], alo[1], bhr);
            }
        }
#pragma unroll
        for (int s = 0; s < 2; ++s)
#pragma unroll
            for (int j = 0; j < 4; ++j) cur[s][j] = nxt[s][j];
    }
#undef LOAD_PAIR

    // --- Epilogue: two 128-row chunks staged through smem ---
    float* stg = (float*)sh;
#pragma unroll
    for (int chunk = 0; chunk < 2; ++chunk) {
        __syncthreads();
        if ((w >> 2) == chunk) {
            int rlb = (w & 3) * 32;
#pragma unroll
            for (int mt = 0; mt < 2; ++mt) {
                int rl0 = rlb + mt * 16 + g4;
#pragma unroll
                for (int na = 0; na < 16; ++na) {
                    int cb = na * 8 + 2 * c4;
                    *(float2*)(stg + rl0 * STG_STRIDE + cb) =
                        make_float2(acc[mt][na][0], acc[mt][na][1]);
                    *(float2*)(stg + (rl0 + 8) * STG_STRIDE + cb) =
                        make_float2(acc[mt][na][2], acc[mt][na][3]);
                }
            }
        }
        __syncthreads();
        int cw = l * 4;
#pragma unroll
        for (int it = 0; it < 16; ++it) {
            int rloc = it * 8 + w;
            int n = n0 + chunk * 128 + rloc;
            if (n < N) {
                float4 v = *(float4*)(stg + rloc * STG_STRIDE + cw);
                int gidx = bid[n];
                float4 cv = *(const float4*)(g_C + (size_t)gidx * 128 + cw);
                v.x += cv.x; v.y += cv.y; v.z += cv.z; v.w += cv.w;
                *(float4*)(out + (size_t)n * 128 + cw) = v;
            }
        }
    }
}

// ---------------------------------------------------------------------------
extern "C" void kernel_launch(void* const* d_in, const int* in_sizes, int n_in,
                              void* d_out, int out_size) {
    const float* x   = (const float*)d_in[0];
    const int*   bid = (const int*)  d_in[1];
    const float* W   = (const float*)d_in[2];
    const float* b   = (const float*)d_in[3];
    float* out = (float*)d_out;
    int N = in_sizes[1];

    cudaFuncSetAttribute(k_gemm, cudaFuncAttributeMaxDynamicSharedMemorySize, SMEM_BYTES);

    k_prep<<<(N + 255) / 256, 256>>>(bid, N, W);
    k_sum<<<(N + 255) / 256, 256>>>(x, bid, N);
    k_ctx<<<G_NUM, 128>>>(W, b);
    k_gemm<<<(N + 255) / 256, 256, SMEM_BYTES>>>(x, bid, out, N);
}

// round 10
// speedup vs baseline: 1.2938x; 1.2938x over previous
#include <cuda_runtime.h>
#include <cuda_bf16.h>
#include <cuda_fp16.h>
#include <cstdint>

#define G_NUM 1024
#define D 128

// ---------------------------------------------------------------------------
// Device scratch
// ---------------------------------------------------------------------------
__device__ int   g_segstart[G_NUM + 1];
__device__ float g_sums[G_NUM * D];
__device__ float g_C[G_NUM * D];
// W1 (fp16) in COLUMN-PERMUTED mma B-fragment layout
__device__ __align__(16) uint32_t g_Bf[8192];

// ---------------------------------------------------------------------------
// Helpers
// ---------------------------------------------------------------------------
__device__ __forceinline__ uint32_t pack_f16(float lo, float hi) {
    uint32_t r;
    asm("cvt.rn.f16x2.f32 %0, %1, %2;" : "=r"(r) : "f"(hi), "f"(lo));
    return r;
}
__device__ __forceinline__ float lo_h(uint32_t p) {
    return __half2float(__ushort_as_half((unsigned short)(p & 0xffff)));
}
__device__ __forceinline__ float hi_h(uint32_t p) {
    return __half2float(__ushort_as_half((unsigned short)(p >> 16)));
}

__device__ __forceinline__ void mma_f16(float* d, const uint32_t* a, const uint32_t* b) {
    asm volatile(
        "mma.sync.aligned.m16n8k16.row.col.f32.f16.f16.f32 "
        "{%0,%1,%2,%3}, {%4,%5,%6,%7}, {%8,%9}, {%0,%1,%2,%3};"
        : "+f"(d[0]), "+f"(d[1]), "+f"(d[2]), "+f"(d[3])
        : "r"(a[0]), "r"(a[1]), "r"(a[2]), "r"(a[3]), "r"(b[0]), "r"(b[1]));
}

// ---------------------------------------------------------------------------
// K1: zero sums + segment boundaries + W1 -> permuted fp16 B-fragments
// ---------------------------------------------------------------------------
__global__ void k_prep(const int* __restrict__ bid, int N, const float* __restrict__ W) {
    int i = blockIdx.x * blockDim.x + threadIdx.x;
    if (i < G_NUM * D) g_sums[i] = 0.f;
    if (i < N) {
        int b = bid[i];
        int prev = (i == 0) ? -1 : bid[i - 1];
        for (int g = prev + 1; g <= b; ++g) g_segstart[g] = i;
        if (i == N - 1)
            for (int g = b + 1; g <= G_NUM; ++g) g_segstart[g] = N;
    }
    if (i < 4096) {
        int ks = i >> 9;
        int na = (i >> 5) & 15;
        int l  = i & 31;
        int c  = l & 3;
        int n  = na * 8 + (l >> 2);
        int k0 = ks * 16 + 4 * c;
        const float* wr = W + (size_t)n * 256;
        g_Bf[i * 2 + 0] = pack_f16(wr[k0],     wr[k0 + 1]);
        g_Bf[i * 2 + 1] = pack_f16(wr[k0 + 2], wr[k0 + 3]);
    }
}

// ---------------------------------------------------------------------------
// K2: tile-parallel segment sums; explicit MLP-8 load batches.
// CTA = 256 rows, 256 thr: warp h reads rows h, h+8, ...; lane q owns
// features 4q..4q+3. Loads batched (8 independent float4) BEFORE any
// accumulate/branch logic so they issue back-to-back.
// ---------------------------------------------------------------------------
__global__ void __launch_bounds__(256)
k_sum(const float* __restrict__ x, const int* __restrict__ bid, int N) {
    __shared__ int sb[256];
    int tid = threadIdx.x;
    int n0 = blockIdx.x * 256;
    sb[tid] = (n0 + tid < N) ? bid[n0 + tid] : -1;
    __syncthreads();

    int h = tid >> 5;
    int q = tid & 31;
    const float* base = x + (size_t)n0 * D + q * 4;

    if ((n0 + 256 <= N) && (sb[0] == sb[255])) {
        // Fast path: single segment covers the whole tile.
        int b0 = sb[0];
        float4 a0 = make_float4(0.f, 0.f, 0.f, 0.f), a1 = a0, a2 = a0, a3 = a0;
#pragma unroll
        for (int m = 0; m < 4; ++m) {
            float4 v[8];
#pragma unroll
            for (int j = 0; j < 8; ++j)
                v[j] = *(const float4*)(base + (size_t)(m * 64 + j * 8 + h) * D);
            a0.x += v[0].x + v[4].x; a0.y += v[0].y + v[4].y;
            a0.z += v[0].z + v[4].z; a0.w += v[0].w + v[4].w;
            a1.x += v[1].x + v[5].x; a1.y += v[1].y + v[5].y;
            a1.z += v[1].z + v[5].z; a1.w += v[1].w + v[5].w;
            a2.x += v[2].x + v[6].x; a2.y += v[2].y + v[6].y;
            a2.z += v[2].z + v[6].z; a2.w += v[2].w + v[6].w;
            a3.x += v[3].x + v[7].x; a3.y += v[3].y + v[7].y;
            a3.z += v[3].z + v[7].z; a3.w += v[3].w + v[7].w;
        }
        a0.x += a1.x + a2.x + a3.x; a0.y += a1.y + a2.y + a3.y;
        a0.z += a1.z + a2.z + a3.z; a0.w += a1.w + a2.w + a3.w;
        float* dst = &g_sums[b0 * D + q * 4];
        atomicAdd(dst + 0, a0.x); atomicAdd(dst + 1, a0.y);
        atomicAdd(dst + 2, a0.z); atomicAdd(dst + 3, a0.w);
        return;
    }

    // Slow path: batch loads first (independent), then flush at boundaries.
    const float4 z4 = make_float4(0.f, 0.f, 0.f, 0.f);
    float4 acc = z4;
    int curbid = sb[h];
#pragma unroll
    for (int m = 0; m < 4; ++m) {
        float4 v[8];
        int bv[8];
#pragma unroll
        for (int j = 0; j < 8; ++j) {
            int r = m * 64 + j * 8 + h;
            bv[j] = sb[r];
            v[j] = (bv[j] >= 0) ? *(const float4*)(base + (size_t)r * D) : z4;
        }
#pragma unroll
        for (int j = 0; j < 8; ++j) {
            if (bv[j] != curbid) {
                if (curbid >= 0) {
                    float* dst = &g_sums[curbid * D + q * 4];
                    atomicAdd(dst + 0, acc.x); atomicAdd(dst + 1, acc.y);
                    atomicAdd(dst + 2, acc.z); atomicAdd(dst + 3, acc.w);
                }
                acc = z4;
                curbid = bv[j];
            }
            acc.x += v[j].x; acc.y += v[j].y; acc.z += v[j].z; acc.w += v[j].w;
        }
    }
    if (curbid >= 0) {
        float* dst = &g_sums[curbid * D + q * 4];
        atomicAdd(dst + 0, acc.x); atomicAdd(dst + 1, acc.y);
        atomicAdd(dst + 2, acc.z); atomicAdd(dst + 3, acc.w);
    }
}

// ---------------------------------------------------------------------------
// K3: C[g] = (sums[g]/cnt) @ W2^T + b
// ---------------------------------------------------------------------------
__global__ void k_ctx(const float* __restrict__ W, const float* __restrict__ b) {
    __shared__ float sm[D];
    int g = blockIdx.x, t = threadIdx.x;
    int s = g_segstart[g], e = g_segstart[g + 1];
    int cnt = e - s;
    float inv = 1.f / (float)(cnt > 0 ? cnt : 1);
    sm[t] = g_sums[g * D + t] * inv;
    __syncthreads();
    float c = b[t];
    const float* wrow = W + (size_t)t * 256 + 128;
#pragma unroll 8
    for (int k = 0; k < D; ++k) c += sm[k] * wrow[k];
    g_C[g * D + t] = c;
}

// ---------------------------------------------------------------------------
// K4: fp16x2 mma.sync GEMM (R8 config: 128x128 tile, 2 CTA/SM)
// ---------------------------------------------------------------------------
#define STG_STRIDE 136
#define SMEM_BYTES (128 * STG_STRIDE * 4)

__global__ void __launch_bounds__(256, 2)
k_gemm(const float* __restrict__ x, const int* __restrict__ bid,
       float* __restrict__ out, int N) {
    extern __shared__ __align__(16) uint32_t sh[];
    uint32_t* shB = sh;                      // [8192] u32 fp16 B frags

    int tid = threadIdx.x;
    int w   = tid >> 5;
    int l   = tid & 31;
    int n0  = blockIdx.x * 128;

#pragma unroll
    for (int i = 0; i < 8; ++i) {
        int q = i * 256 + tid;
        *(uint4*)(shB + q * 4) = *(const uint4*)(g_Bf + q * 4);
    }
    __syncthreads();

    int g4 = l >> 2, c4 = l & 3;
    int r0 = n0 + w * 16 + g4;
    int r1 = r0 + 8;
    const float* p0 = x + (size_t)r0 * 128;
    const float* p1 = x + (size_t)r1 * 128;
    bool full = (n0 + 128) <= N;
    bool vr0 = full || (r0 < N), vr1 = full || (r1 < N);
    const float4 z4 = make_float4(0.f, 0.f, 0.f, 0.f);

    float acc[16][4];
#pragma unroll
    for (int na = 0; na < 16; ++na)
#pragma unroll
        for (int j = 0; j < 4; ++j) acc[na][j] = 0.f;

    float4 cur[2][2], nxt[2][2];

#define LOAD_PAIR(dst, kp)                                                     \
    do {                                                                       \
        _Pragma("unroll")                                                      \
        for (int s_ = 0; s_ < 2; ++s_) {                                       \
            int k0_ = ((kp) * 2 + s_) * 16 + 4 * c4;                           \
            dst[s_][0] = vr0 ? *(const float4*)(p0 + k0_) : z4;                \
            dst[s_][1] = vr1 ? *(const float4*)(p1 + k0_) : z4;                \
        }                                                                      \
    } while (0)

    LOAD_PAIR(cur, 0);

#pragma unroll
    for (int kp = 0; kp < 4; ++kp) {
        if (kp < 3) LOAD_PAIR(nxt, kp + 1);

#pragma unroll
        for (int s = 0; s < 2; ++s) {
            int ks = kp * 2 + s;
            float4 u = cur[s][0];
            float4 v = cur[s][1];
            uint32_t ahi[4], alo[4];
            ahi[0] = pack_f16(u.x, u.y);
            ahi[1] = pack_f16(v.x, v.y);
            ahi[2] = pack_f16(u.z, u.w);
            ahi[3] = pack_f16(v.z, v.w);
            alo[0] = pack_f16(u.x - lo_h(ahi[0]), u.y - hi_h(ahi[0]));
            alo[1] = pack_f16(v.x - lo_h(ahi[1]), v.y - hi_h(ahi[1]));
            alo[2] = pack_f16(u.z - lo_h(ahi[2]), u.w - hi_h(ahi[2]));
            alo[3] = pack_f16(v.z - lo_h(ahi[3]), v.w - hi_h(ahi[3]));

            const uint32_t* bks = shB + ks * 16 * 64;
#pragma unroll
            for (int na = 0; na < 16; ++na) {
                uint2 bh = *(const uint2*)(bks + na * 64 + l * 2);
                uint32_t bhr[2] = {bh.x, bh.y};
                mma_f16(acc[na], ahi, bhr);
                mma_f16(acc[na], alo, bhr);
            }
        }
#pragma unroll
        for (int s = 0; s < 2; ++s)
#pragma unroll
            for (int j = 0; j < 2; ++j) cur[s][j] = nxt[s][j];
    }
#undef LOAD_PAIR

    float* stg = (float*)sh;
    __syncthreads();
    {
        int rl0 = w * 16 + g4;
#pragma unroll
        for (int na = 0; na < 16; ++na) {
            int cb = na * 8 + 2 * c4;
            *(float2*)(stg + rl0 * STG_STRIDE + cb) =
                make_float2(acc[na][0], acc[na][1]);
            *(float2*)(stg + (rl0 + 8) * STG_STRIDE + cb) =
                make_float2(acc[na][2], acc[na][3]);
        }
    }
    __syncthreads();
    {
        int cw = l * 4;
#pragma unroll
        for (int it = 0; it < 16; ++it) {
            int rloc = it * 8 + w;
            int n = n0 + rloc;
            if (n < N) {
                float4 v = *(float4*)(stg + rloc * STG_STRIDE + cw);
                int gidx = bid[n];
                float4 cv = *(const float4*)(g_C + (size_t)gidx * 128 + cw);
                v.x += cv.x; v.y += cv.y; v.z += cv.z; v.w += cv.w;
                *(float4*)(out + (size_t)n * 128 + cw) = v;
            }
        }
    }
}

// ---------------------------------------------------------------------------
extern "C" void kernel_launch(void* const* d_in, const int* in_sizes, int n_in,
                              void* d_out, int out_size) {
    const float* x   = (const float*)d_in[0];
    const int*   bid = (const int*)  d_in[1];
    const float* W   = (const float*)d_in[2];
    const float* b   = (const float*)d_in[3];
    float* out = (float*)d_out;
    int N = in_sizes[1];

    cudaFuncSetAttribute(k_gemm, cudaFuncAttributeMaxDynamicSharedMemorySize, SMEM_BYTES);

    k_prep<<<(N + 255) / 256, 256>>>(bid, N, W);
    k_sum<<<(N + 255) / 256, 256>>>(x, bid, N);
    k_ctx<<<G_NUM, 128>>>(W, b);
    k_gemm<<<(N + 127) / 128, 256, SMEM_BYTES>>>(x, bid, out, N);
}

// round 11
// speedup vs baseline: 1.6275x; 1.2579x over previous
#include <cuda_runtime.h>
#include <cuda_bf16.h>
#include <cuda_fp16.h>
#include <cstdint>

#define G_NUM 1024
#define D 128

// ---------------------------------------------------------------------------
// Device scratch
// ---------------------------------------------------------------------------
__device__ int   g_segstart[G_NUM + 1];
__device__ float g_sums[G_NUM * D];
__device__ float g_C[G_NUM * D];
__device__ float g_W2t[D * D];                 // W2 transposed: [k][t]
__device__ __align__(16) uint32_t g_Bf[8192];  // W1 fp16 B-fragments (col-permuted)

// ---------------------------------------------------------------------------
// Helpers
// ---------------------------------------------------------------------------
__device__ __forceinline__ uint32_t smem_u32(const void* p) {
    return (uint32_t)__cvta_generic_to_shared((void*)p);
}
__device__ __forceinline__ uint32_t pack_f16(float lo, float hi) {
    uint32_t r;
    asm("cvt.rn.f16x2.f32 %0, %1, %2;" : "=r"(r) : "f"(hi), "f"(lo));
    return r;
}
__device__ __forceinline__ float lo_h(uint32_t p) {
    return __half2float(__ushort_as_half((unsigned short)(p & 0xffff)));
}
__device__ __forceinline__ float hi_h(uint32_t p) {
    return __half2float(__ushort_as_half((unsigned short)(p >> 16)));
}
__device__ __forceinline__ void mma_f16(float* d, const uint32_t* a, const uint32_t* b) {
    asm volatile(
        "mma.sync.aligned.m16n8k16.row.col.f32.f16.f16.f32 "
        "{%0,%1,%2,%3}, {%4,%5,%6,%7}, {%8,%9}, {%0,%1,%2,%3};"
        : "+f"(d[0]), "+f"(d[1]), "+f"(d[2]), "+f"(d[3])
        : "r"(a[0]), "r"(a[1]), "r"(a[2]), "r"(a[3]), "r"(b[0]), "r"(b[1]));
}
__device__ __forceinline__ void cp16(uint32_t dst, const void* src) {
    asm volatile("cp.async.cg.shared.global [%0], [%1], 16;"
                 :: "r"(dst), "l"(src) : "memory");
}
#define CP_COMMIT() asm volatile("cp.async.commit_group;" ::: "memory")
#define CP_WAIT(n)  asm volatile("cp.async.wait_group %0;" :: "n"(n) : "memory")

// ---------------------------------------------------------------------------
// K1: zero sums + segment boundaries + W1 B-fragments + W2 transpose
// ---------------------------------------------------------------------------
__global__ void k_prep(const int* __restrict__ bid, int N, const float* __restrict__ W) {
    int i = blockIdx.x * blockDim.x + threadIdx.x;
    if (i < G_NUM * D) g_sums[i] = 0.f;
    if (i < N) {
        int b = bid[i];
        int prev = (i == 0) ? -1 : bid[i - 1];
        for (int g = prev + 1; g <= b; ++g) g_segstart[g] = i;
        if (i == N - 1)
            for (int g = b + 1; g <= G_NUM; ++g) g_segstart[g] = N;
    }
    if (i < 4096) {
        int ks = i >> 9;
        int na = (i >> 5) & 15;
        int l  = i & 31;
        int c  = l & 3;
        int n  = na * 8 + (l >> 2);
        int k0 = ks * 16 + 4 * c;
        const float* wr = W + (size_t)n * 256;
        g_Bf[i * 2 + 0] = pack_f16(wr[k0],     wr[k0 + 1]);
        g_Bf[i * 2 + 1] = pack_f16(wr[k0 + 2], wr[k0 + 3]);
    }
    if (i < D * D) {
        int k = i >> 7, t = i & 127;
        g_W2t[i] = W[(size_t)t * 256 + 128 + k];
    }
}

// ---------------------------------------------------------------------------
// K2: segment sums via cp.async double-buffered smem pipeline.
// CTA = 256 rows, 8 chunks of 32 rows (16KB each). Warp h reduces rows
// {h, h+8, h+16, h+24} of each chunk; lane q owns features 4q..4q+3.
// ---------------------------------------------------------------------------
__global__ void __launch_bounds__(256)
k_sum(const float* __restrict__ x, const int* __restrict__ bid, int N) {
    __shared__ __align__(16) float buf[2][32 * 128];
    __shared__ int sb[256];
    int tid = threadIdx.x;
    int n0 = blockIdx.x * 256;
    sb[tid] = (n0 + tid < N) ? bid[n0 + tid] : -1;
    __syncthreads();

    int h = tid >> 5;
    int q = tid & 31;
    const float4 z4 = make_float4(0.f, 0.f, 0.f, 0.f);
    float4 acc = z4;
    int curbid = sb[h];

    if (n0 + 256 > N) {
        // Tail CTA (at most one): simple guarded path.
#pragma unroll 4
        for (int r = h; r < 256; r += 8) {
            int bv = sb[r];
            if (bv != curbid) {
                if (curbid >= 0) {
                    float* dst = &g_sums[curbid * D + q * 4];
                    atomicAdd(dst + 0, acc.x); atomicAdd(dst + 1, acc.y);
                    atomicAdd(dst + 2, acc.z); atomicAdd(dst + 3, acc.w);
                }
                acc = z4; curbid = bv;
            }
            if (bv >= 0) {
                float4 v = *(const float4*)(x + (size_t)(n0 + r) * D + q * 4);
                acc.x += v.x; acc.y += v.y; acc.z += v.z; acc.w += v.w;
            }
        }
        if (curbid >= 0) {
            float* dst = &g_sums[curbid * D + q * 4];
            atomicAdd(dst + 0, acc.x); atomicAdd(dst + 1, acc.y);
            atomicAdd(dst + 2, acc.z); atomicAdd(dst + 3, acc.w);
        }
        return;
    }

    const float4* src = (const float4*)(x + (size_t)n0 * 128);   // 8192 float4s
    uint32_t sb0 = smem_u32(&buf[0][0]);
    uint32_t sb1 = smem_u32(&buf[1][0]);

    // Stage chunk c (1024 float4s) into buffer s: 4 cp.async per thread.
#define STAGE(c, s)                                                            \
    do {                                                                       \
        uint32_t _d = ((s) ? sb1 : sb0) + (uint32_t)tid * 16;                  \
        const float4* _p = src + (c) * 1024 + tid;                             \
        cp16(_d + 0 * 4096, _p + 0 * 256);                                     \
        cp16(_d + 1 * 4096, _p + 1 * 256);                                     \
        cp16(_d + 2 * 4096, _p + 2 * 256);                                     \
        cp16(_d + 3 * 4096, _p + 3 * 256);                                     \
        CP_COMMIT();                                                           \
    } while (0)

    STAGE(0, 0);
#pragma unroll
    for (int c = 0; c < 8; ++c) {
        if (c < 7) {
            STAGE(c + 1, (c + 1) & 1);
            CP_WAIT(1);
        } else {
            CP_WAIT(0);
        }
        __syncthreads();
        const float* bp = buf[c & 1];
#pragma unroll
        for (int rr = 0; rr < 4; ++rr) {
            int r = rr * 8 + h;
            int bv = sb[c * 32 + r];
            float4 v = *(const float4*)(bp + r * 128 + q * 4);
            if (bv != curbid) {
                if (curbid >= 0) {
                    float* dst = &g_sums[curbid * D + q * 4];
                    atomicAdd(dst + 0, acc.x); atomicAdd(dst + 1, acc.y);
                    atomicAdd(dst + 2, acc.z); atomicAdd(dst + 3, acc.w);
                }
                acc = z4; curbid = bv;
            }
            acc.x += v.x; acc.y += v.y; acc.z += v.z; acc.w += v.w;
        }
        __syncthreads();   // protect buffer re-stage next iteration
    }
#undef STAGE

    if (curbid >= 0) {
        float* dst = &g_sums[curbid * D + q * 4];
        atomicAdd(dst + 0, acc.x); atomicAdd(dst + 1, acc.y);
        atomicAdd(dst + 2, acc.z); atomicAdd(dst + 3, acc.w);
    }
}

// ---------------------------------------------------------------------------
// K3: C[g] = (sums[g]/cnt) @ W2^T + b, coalesced via g_W2t
// ---------------------------------------------------------------------------
__global__ void k_ctx(const float* __restrict__ b) {
    __shared__ float sm[D];
    int g = blockIdx.x, t = threadIdx.x;
    int s = g_segstart[g], e = g_segstart[g + 1];
    int cnt = e - s;
    float inv = 1.f / (float)(cnt > 0 ? cnt : 1);
    sm[t] = g_sums[g * D + t] * inv;
    __syncthreads();
    float c = b[t];
#pragma unroll 8
    for (int k = 0; k < D; ++k) c += sm[k] * g_W2t[k * 128 + t];
    g_C[g * D + t] = c;
}

// ---------------------------------------------------------------------------
// K4: fp16x2 mma.sync GEMM (unchanged R8/R10 config: 128x128, 2 CTA/SM)
// ---------------------------------------------------------------------------
#define STG_STRIDE 136
#define SMEM_BYTES (128 * STG_STRIDE * 4)

__global__ void __launch_bounds__(256, 2)
k_gemm(const float* __restrict__ x, const int* __restrict__ bid,
       float* __restrict__ out, int N) {
    extern __shared__ __align__(16) uint32_t sh[];
    uint32_t* shB = sh;

    int tid = threadIdx.x;
    int w   = tid >> 5;
    int l   = tid & 31;
    int n0  = blockIdx.x * 128;

#pragma unroll
    for (int i = 0; i < 8; ++i) {
        int q = i * 256 + tid;
        *(uint4*)(shB + q * 4) = *(const uint4*)(g_Bf + q * 4);
    }
    __syncthreads();

    int g4 = l >> 2, c4 = l & 3;
    int r0 = n0 + w * 16 + g4;
    int r1 = r0 + 8;
    const float* p0 = x + (size_t)r0 * 128;
    const float* p1 = x + (size_t)r1 * 128;
    bool full = (n0 + 128) <= N;
    bool vr0 = full || (r0 < N), vr1 = full || (r1 < N);
    const float4 z4 = make_float4(0.f, 0.f, 0.f, 0.f);

    float acc[16][4];
#pragma unroll
    for (int na = 0; na < 16; ++na)
#pragma unroll
        for (int j = 0; j < 4; ++j) acc[na][j] = 0.f;

    float4 cur[2][2], nxt[2][2];

#define LOAD_PAIR(dst, kp)                                                     \
    do {                                                                       \
        _Pragma("unroll")                                                      \
        for (int s_ = 0; s_ < 2; ++s_) {                                       \
            int k0_ = ((kp) * 2 + s_) * 16 + 4 * c4;                           \
            dst[s_][0] = vr0 ? *(const float4*)(p0 + k0_) : z4;                \
            dst[s_][1] = vr1 ? *(const float4*)(p1 + k0_) : z4;                \
        }                                                                      \
    } while (0)

    LOAD_PAIR(cur, 0);

#pragma unroll
    for (int kp = 0; kp < 4; ++kp) {
        if (kp < 3) LOAD_PAIR(nxt, kp + 1);

#pragma unroll
        for (int s = 0; s < 2; ++s) {
            int ks = kp * 2 + s;
            float4 u = cur[s][0];
            float4 v = cur[s][1];
            uint32_t ahi[4], alo[4];
            ahi[0] = pack_f16(u.x, u.y);
            ahi[1] = pack_f16(v.x, v.y);
            ahi[2] = pack_f16(u.z, u.w);
            ahi[3] = pack_f16(v.z, v.w);
            alo[0] = pack_f16(u.x - lo_h(ahi[0]), u.y - hi_h(ahi[0]));
            alo[1] = pack_f16(v.x - lo_h(ahi[1]), v.y - hi_h(ahi[1]));
            alo[2] = pack_f16(u.z - lo_h(ahi[2]), u.w - hi_h(ahi[2]));
            alo[3] = pack_f16(v.z - lo_h(ahi[3]), v.w - hi_h(ahi[3]));

            const uint32_t* bks = shB + ks * 16 * 64;
#pragma unroll
            for (int na = 0; na < 16; ++na) {
                uint2 bh = *(const uint2*)(bks + na * 64 + l * 2);
                uint32_t bhr[2] = {bh.x, bh.y};
                mma_f16(acc[na], ahi, bhr);
                mma_f16(acc[na], alo, bhr);
            }
        }
#pragma unroll
        for (int s = 0; s < 2; ++s)
#pragma unroll
            for (int j = 0; j < 2; ++j) cur[s][j] = nxt[s][j];
    }
#undef LOAD_PAIR

    float* stg = (float*)sh;
    __syncthreads();
    {
        int rl0 = w * 16 + g4;
#pragma unroll
        for (int na = 0; na < 16; ++na) {
            int cb = na * 8 + 2 * c4;
            *(float2*)(stg + rl0 * STG_STRIDE + cb) =
                make_float2(acc[na][0], acc[na][1]);
            *(float2*)(stg + (rl0 + 8) * STG_STRIDE + cb) =
                make_float2(acc[na][2], acc[na][3]);
        }
    }
    __syncthreads();
    {
        int cw = l * 4;
#pragma unroll
        for (int it = 0; it < 16; ++it) {
            int rloc = it * 8 + w;
            int n = n0 + rloc;
            if (n < N) {
                float4 v = *(float4*)(stg + rloc * STG_STRIDE + cw);
                int gidx = bid[n];
                float4 cv = *(const float4*)(g_C + (size_t)gidx * 128 + cw);
                v.x += cv.x; v.y += cv.y; v.z += cv.z; v.w += cv.w;
                *(float4*)(out + (size_t)n * 128 + cw) = v;
            }
        }
    }
}

// ---------------------------------------------------------------------------
extern "C" void kernel_launch(void* const* d_in, const int* in_sizes, int n_in,
                              void* d_out, int out_size) {
    const float* x   = (const float*)d_in[0];
    const int*   bid = (const int*)  d_in[1];
    const float* W   = (const float*)d_in[2];
    const float* b   = (const float*)d_in[3];
    float* out = (float*)d_out;
    int N = in_sizes[1];

    cudaFuncSetAttribute(k_gemm, cudaFuncAttributeMaxDynamicSharedMemorySize, SMEM_BYTES);

    k_prep<<<(N + 255) / 256, 256>>>(bid, N, W);
    k_sum<<<(N + 255) / 256, 256>>>(x, bid, N);
    k_ctx<<<G_NUM, 128>>>(b);
    k_gemm<<<(N + 127) / 128, 256, SMEM_BYTES>>>(x, bid, out, N);
}